// round 13
// baseline (speedup 1.0000x reference)
#include <cuda_runtime.h>
#include <cstdint>
#include <cstddef>

#define T_STEPS 2048
#define B_SIZE  256
#define I_SIZE  64
#define H_SIZE  128

// Scratch: input projections x@Wi + bi, layout [T][B][3*H] (805 MB)
__device__ float g_xproj[(size_t)T_STEPS * B_SIZE * 3 * H_SIZE];
// Scratch: hidden states hs [T][B][H] (268 MB) for deferred classifier
__device__ float g_hs[(size_t)T_STEPS * B_SIZE * H_SIZE];

__device__ __forceinline__ float sigmoidf_(float x) {
    return 1.0f / (1.0f + __expf(-x));
}
__device__ __forceinline__ float tanhf_(float x) {
    return 1.0f - 2.0f / (1.0f + __expf(2.0f * x));
}

// ---- packed f32x2 helpers (Blackwell FFMA2 / FADD2) ------------------------
__device__ __forceinline__ unsigned long long fma2_(unsigned long long a,
                                                    unsigned long long b,
                                                    unsigned long long c) {
    unsigned long long d;
    asm("fma.rn.f32x2 %0, %1, %2, %3;" : "=l"(d) : "l"(a), "l"(b), "l"(c));
    return d;
}
__device__ __forceinline__ unsigned long long add2_(unsigned long long a,
                                                    unsigned long long b) {
    unsigned long long d;
    asm("add.rn.f32x2 %0, %1, %2;" : "=l"(d) : "l"(a), "l"(b));
    return d;
}
__device__ __forceinline__ unsigned long long dup2_(float x) {
    unsigned long long d;
    asm("mov.b64 %0, {%1, %1};" : "=l"(d) : "f"(x));
    return d;
}
__device__ __forceinline__ unsigned long long pack2_(float a, float b) {
    unsigned long long d;
    asm("mov.b64 %0, {%1, %2};" : "=l"(d) : "f"(a), "f"(b));
    return d;
}
__device__ __forceinline__ float2 unpack2_(unsigned long long v) {
    float2 r;
    asm("mov.b64 {%0, %1}, %2;" : "=f"(r.x), "=f"(r.y) : "l"(v));
    return r;
}

// ============================================================================
// Phase 1: xproj — R10 inner scheme, but each block does 2 consecutive
// 64-row tiles with ONE W load (halves W traffic + load bubbles).
// grid = (4096, 3), 128 threads, 3 blocks/SM, SMEM 48KB.
// ============================================================================
#define XS_IDX(i, row) ((i) * 64 + ((row) ^ ((i) & 60)))

__global__ __launch_bounds__(128, 3) void xproj_kernel(
    const float* __restrict__ x,
    const float* __restrict__ Wir, const float* __restrict__ Wiz, const float* __restrict__ Win,
    const float* __restrict__ bir, const float* __restrict__ biz, const float* __restrict__ bin_)
{
    __shared__ __align__(16) float xs[I_SIZE * 64];       // 16384 B
    __shared__ __align__(16) float ws[I_SIZE * H_SIZE];   // 32768 B

    const int g = blockIdx.y;
    const float* __restrict__ W    = (g == 0) ? Wir : (g == 1) ? Wiz : Win;
    const float* __restrict__ bias = (g == 0) ? bir : (g == 1) ? biz : bin_;

    const int tid = threadIdx.x;

    // Load W [64 x 128] once per block.
    const float4* __restrict__ Wg4 = (const float4*)W;
    #pragma unroll
    for (int s = 0; s < 16; s++) {
        int idx4 = tid + 128 * s;
        ((float4*)ws)[idx4] = Wg4[idx4];
    }

    const int tr = tid & 15;
    const int tc = tid >> 4;
    const int r0 = tr * 4;
    const int c0 = tc * 16;

    // Bias once per block (L1/L2-cached).
    const float4* __restrict__ bp = (const float4*)(bias + c0);
    float4 b0 = bp[0], b1 = bp[1], b2 = bp[2], b3 = bp[3];
    float bv[16] = {b0.x, b0.y, b0.z, b0.w, b1.x, b1.y, b1.z, b1.w,
                    b2.x, b2.y, b2.z, b2.w, b3.x, b3.y, b3.z, b3.w};

    #pragma unroll
    for (int half = 0; half < 2; half++) {
        const size_t r_base = ((size_t)blockIdx.x * 2 + half) * 64;

        if (half) __syncthreads();   // protect xs from previous half's readers

        const float4* __restrict__ xg4 = (const float4*)(x + r_base * I_SIZE);
        #pragma unroll
        for (int s = 0; s < 8; s++) {
            int idx4 = tid + 128 * s;            // 0..1023 float4s
            float4 v = xg4[idx4];
            int row = idx4 >> 4;
            int i0  = (idx4 & 15) * 4;
            xs[XS_IDX(i0 + 0, row)] = v.x;
            xs[XS_IDX(i0 + 1, row)] = v.y;
            xs[XS_IDX(i0 + 2, row)] = v.z;
            xs[XS_IDX(i0 + 3, row)] = v.w;
        }
        __syncthreads();   // xs (and, first half, ws) visible

        unsigned long long accp[4][8];
        #pragma unroll
        for (int r = 0; r < 4; r++)
            #pragma unroll
            for (int c = 0; c < 8; c++)
                accp[r][c] = 0ull;

        #pragma unroll 4
        for (int k = 0; k < I_SIZE; k++) {
            float4 xa = *(const float4*)&xs[XS_IDX(k, r0)];
            const ulonglong2* wr = (const ulonglong2*)&ws[k * H_SIZE + c0];
            ulonglong2 wq0 = wr[0], wq1 = wr[1], wq2 = wr[2], wq3 = wr[3];
            unsigned long long wp[8] = {wq0.x, wq0.y, wq1.x, wq1.y,
                                        wq2.x, wq2.y, wq3.x, wq3.y};
            unsigned long long xd[4] = {dup2_(xa.x), dup2_(xa.y), dup2_(xa.z), dup2_(xa.w)};
            #pragma unroll
            for (int r = 0; r < 4; r++)
                #pragma unroll
                for (int c = 0; c < 8; c++)
                    accp[r][c] = fma2_(xd[r], wp[c], accp[r][c]);
        }

        #pragma unroll
        for (int r = 0; r < 4; r++) {
            size_t row = r_base + (size_t)(r0 + r);
            float* op = g_xproj + row * (3 * H_SIZE) + g * H_SIZE + c0;
            #pragma unroll
            for (int q = 0; q < 4; q++) {
                float2 pa = unpack2_(accp[r][2 * q + 0]);
                float2 pb = unpack2_(accp[r][2 * q + 1]);
                float4 o;
                o.x = pa.x + bv[4 * q + 0];
                o.y = pa.y + bv[4 * q + 1];
                o.z = pb.x + bv[4 * q + 2];
                o.w = pb.y + bv[4 * q + 3];
                *(float4*)(op + 4 * q) = o;
            }
        }
    }
}

// ============================================================================
// Phase 2: persistent per-batch GRU recurrence (R12 protocol, trimmed chain).
// grid = 128 blocks (2 batch rows each), 384 threads.
//  - packed add.rn.f32x2 reduction after the dot (shorter dependency tree)
//  - gate-2 pre-adds bhn into stored n-dot; (a1+bhn, xn1) packed as float2
//  - blend h' = n + z*(h-n) (2 FMA)
//  - branchless x(t+1) prefetch via clamped index
// ============================================================================
__global__ __launch_bounds__(384, 1) void gru_kernel(
    const float* __restrict__ Whr, const float* __restrict__ Whz, const float* __restrict__ Whn,
    const float* __restrict__ bhn)
{
    __shared__ __align__(16) float h_s[2][H_SIZE];
    __shared__ float r_s[2][H_SIZE];
    __shared__ float z0_s[H_SIZE];             // z row 0 (gate-1 keeps z1 in reg)
    __shared__ __align__(8) float2 ax1_s[H_SIZE];  // (a1 + bhn, xn1) for row 1

    const int tid = threadIdx.x;
    const int g   = tid >> 7;       // 0=r, 1=z, 2=n
    const int j   = tid & 127;
    const int b0  = blockIdx.x * 2;

    const float* __restrict__ Wh = (g == 0) ? Whr : (g == 1) ? Whz : Whn;

    // Register-resident weight column packed over k pairs.
    unsigned long long w2[H_SIZE / 2];
    #pragma unroll
    for (int m = 0; m < H_SIZE / 2; m++)
        w2[m] = pack2_(Wh[(2 * m) * H_SIZE + j], Wh[(2 * m + 1) * H_SIZE + j]);

    const float bhn_j = bhn[j];

    if (tid < 2 * H_SIZE) ((float*)h_s)[tid] = 0.0f;   // h0 = 0
    __syncthreads();

    const float* __restrict__ xp = g_xproj + (size_t)b0 * (3 * H_SIZE) + g * H_SIZE + j;
    const size_t step_stride = (size_t)B_SIZE * 3 * H_SIZE;

    const ulonglong2* __restrict__ h0q = (const ulonglong2*)h_s[0];
    const ulonglong2* __restrict__ h1q = (const ulonglong2*)h_s[1];

    float x0 = xp[0];
    float x1 = xp[3 * H_SIZE];

    for (int t = 0; t < T_STEPS; t++) {
        // branchless prefetch of x(t+1) (t = T-1 re-reads last step, unused)
        int tn = (t + 1 < T_STEPS) ? (t + 1) : t;
        const float* xq = xp + (size_t)tn * step_stride;
        float nx0 = xq[0];
        float nx1 = xq[3 * H_SIZE];

        // acc[row] = sum_k h[row][k] * Wh[k][j] — packed over k, 8 chains.
        unsigned long long p00 = 0ull, p01 = 0ull, p02 = 0ull, p03 = 0ull;
        unsigned long long p10 = 0ull, p11 = 0ull, p12 = 0ull, p13 = 0ull;
        #pragma unroll
        for (int m = 0; m < 16; m++) {
            ulonglong2 va0 = h0q[2 * m];
            ulonglong2 vb0 = h0q[2 * m + 1];
            ulonglong2 va1 = h1q[2 * m];
            ulonglong2 vb1 = h1q[2 * m + 1];
            p00 = fma2_(va0.x, w2[4 * m + 0], p00);
            p01 = fma2_(va0.y, w2[4 * m + 1], p01);
            p02 = fma2_(vb0.x, w2[4 * m + 2], p02);
            p03 = fma2_(vb0.y, w2[4 * m + 3], p03);
            p10 = fma2_(va1.x, w2[4 * m + 0], p10);
            p11 = fma2_(va1.y, w2[4 * m + 1], p11);
            p12 = fma2_(vb1.x, w2[4 * m + 2], p12);
            p13 = fma2_(vb1.y, w2[4 * m + 3], p13);
        }
        // packed reduction: 3 packed adds per row, then one unpack+add
        unsigned long long s0 = add2_(add2_(p00, p01), add2_(p02, p03));
        unsigned long long s1 = add2_(add2_(p10, p11), add2_(p12, p13));
        float2 u0 = unpack2_(s0);
        float2 u1 = unpack2_(s1);
        float acc0 = u0.x + u0.y;
        float acc1 = u1.x + u1.y;

        float z1r = 0.0f;
        if (g == 0) {
            r_s[0][j] = sigmoidf_(x0 + acc0);
            r_s[1][j] = sigmoidf_(x1 + acc1);
        } else if (g == 1) {
            z0_s[j] = sigmoidf_(x0 + acc0);
            z1r     = sigmoidf_(x1 + acc1);
        } else {
            float2 ax;
            ax.x = acc1 + bhn_j;           // pre-add bias
            ax.y = x1;
            ax1_s[j] = ax;
        }
        __syncthreads();   // r, z0, (a1+bhn, xn1) ready

        if (g == 2) {
            // row 0 update (acc0, x0 live in regs)
            float h0o = h_s[0][j];
            float n0  = tanhf_(fmaf(r_s[0][j], acc0 + bhn_j, x0));
            float z0  = z0_s[j];
            float hn0 = fmaf(z0, h0o - n0, n0);   // n + z*(h-n)
            h_s[0][j] = hn0;
            g_hs[((size_t)t * B_SIZE + b0) * H_SIZE + j] = hn0;
        } else if (g == 1) {
            // row 1 update (z1 live in reg)
            float h1o = h_s[1][j];
            float2 ax = ax1_s[j];
            float n1  = tanhf_(fmaf(r_s[1][j], ax.x, ax.y));
            float hn1 = fmaf(z1r, h1o - n1, n1);
            h_s[1][j] = hn1;
            g_hs[((size_t)t * B_SIZE + b0 + 1) * H_SIZE + j] = hn1;
        }
        __syncthreads();   // h_new ready for next step's dot

        x0 = nx0;
        x1 = nx1;
    }
}

// ============================================================================
// Phase 3: classifier out[o] = sigmoid(dot(hs[o,:], Wc) + bc).
// Warp per output; memory-bound (268 MB streamed).
// ============================================================================
__global__ __launch_bounds__(256) void cls_kernel(
    const float* __restrict__ Wc, const float* __restrict__ bc,
    float* __restrict__ out)
{
    const int lane = threadIdx.x & 31;
    const size_t o = (size_t)blockIdx.x * 8 + (threadIdx.x >> 5);

    float4 h4 = *(const float4*)&g_hs[o * H_SIZE + lane * 4];
    float4 w4 = *(const float4*)&Wc[lane * 4];
    float v = fmaf(h4.x, w4.x, fmaf(h4.y, w4.y, fmaf(h4.z, w4.z, h4.w * w4.w)));
    #pragma unroll
    for (int off = 16; off > 0; off >>= 1)
        v += __shfl_down_sync(0xffffffffu, v, off);
    if (lane == 0) out[o] = sigmoidf_(v + bc[0]);
}

// ============================================================================
extern "C" void kernel_launch(void* const* d_in, const int* in_sizes, int n_in,
                              void* d_out, int out_size)
{
    const float* x    = (const float*)d_in[0];
    const float* Wir  = (const float*)d_in[1];
    const float* Wiz  = (const float*)d_in[2];
    const float* Win  = (const float*)d_in[3];
    const float* bir  = (const float*)d_in[4];
    const float* biz  = (const float*)d_in[5];
    const float* bin_ = (const float*)d_in[6];
    const float* Whr  = (const float*)d_in[7];
    const float* Whz  = (const float*)d_in[8];
    const float* Whn  = (const float*)d_in[9];
    const float* bhn  = (const float*)d_in[10];
    const float* Wc   = (const float*)d_in[11];
    const float* bc   = (const float*)d_in[12];
    float* out = (float*)d_out;

    // Phase 1: input projections, 2 tiles per block (W amortized).
    dim3 grid1((T_STEPS * B_SIZE) / 128, 3);
    xproj_kernel<<<grid1, 128>>>(x, Wir, Wiz, Win, bir, biz, bin_);

    // Phase 2: sequential recurrence, batch-parallel across 128 blocks.
    gru_kernel<<<B_SIZE / 2, 384>>>(Whr, Whz, Whn, bhn);

    // Phase 3: classifier over all T*B hidden states.
    cls_kernel<<<(T_STEPS * B_SIZE) / 8, 256>>>(Wc, bc, out);
}